// round 1
// baseline (speedup 1.0000x reference)
#include <cuda_runtime.h>

// Windowed local attention, k=7, H=W=256, C=32, fp32.
// Tile: 32x4 pixels per 128-thread block. Halo 38x10 per channel.
// Smem layout: [C][CS] channel-major, CS=381 (odd pad -> conflict-free staging).

#define H_IMG 256
#define W_IMG 256
#define C 32
#define K 7
#define PAD 3
#define TX 32
#define TY 4
#define HW 38              // TX + K - 1
#define HH 10              // TY + K - 1
#define CS 381             // HW*HH = 380, +1 pad (odd)
#define NTHREADS 128
#define SMEM_BYTES (2 * C * CS * 4)

__global__ __launch_bounds__(NTHREADS, 2)
void local_attn_kernel(const float* __restrict__ main_in,
                       const float* __restrict__ ref_in,
                       const float* __restrict__ val_in,
                       float* __restrict__ out) {
    extern __shared__ float smem[];
    float* refs = smem;              // [C][CS]
    float* vals = smem + C * CS;     // [C][CS]
    float* trans = smem;             // reused after pass1: [128][33]

    const int tid = threadIdx.x;
    const int bx = blockIdx.x, by = blockIdx.y;
    const int px = tid & 31;         // 0..31 (lane)
    const int py = tid >> 5;         // 0..3  (warp id)

    // ---- Stage ref/val halos into smem, channel-major, zero-padded OOB ----
    for (int idx = tid; idx < HW * HH * (C / 4); idx += NTHREADS) {
        int cg = idx & 7;                 // channel group (4 ch each)
        int wp = (idx >> 3) % HW;
        int hp = (idx >> 3) / HW;
        int gw = bx * TX - PAD + wp;
        int gh = by * TY - PAD + hp;
        float4 r = make_float4(0.f, 0.f, 0.f, 0.f);
        float4 v = make_float4(0.f, 0.f, 0.f, 0.f);
        if (gw >= 0 && gw < W_IMG && gh >= 0 && gh < H_IMG) {
            int g = ((gh << 8) + gw) * C + (cg << 2);
            r = *reinterpret_cast<const float4*>(ref_in + g);
            v = *reinterpret_cast<const float4*>(val_in + g);
        }
        int s = hp * HW + wp;
        int c0 = cg << 2;
        refs[(c0 + 0) * CS + s] = r.x;
        refs[(c0 + 1) * CS + s] = r.y;
        refs[(c0 + 2) * CS + s] = r.z;
        refs[(c0 + 3) * CS + s] = r.w;
        vals[(c0 + 0) * CS + s] = v.x;
        vals[(c0 + 1) * CS + s] = v.y;
        vals[(c0 + 2) * CS + s] = v.z;
        vals[(c0 + 3) * CS + s] = v.w;
    }

    // ---- Load this pixel's query (main) into registers ----
    float m[C];
    {
        int gh = by * TY + py;
        int gw = bx * TX + px;
        int g = ((gh << 8) + gw) * C;
        #pragma unroll
        for (int i = 0; i < C / 4; i++) {
            float4 t = *reinterpret_cast<const float4*>(main_in + g + 4 * i);
            m[4 * i + 0] = t.x;
            m[4 * i + 1] = t.y;
            m[4 * i + 2] = t.z;
            m[4 * i + 3] = t.w;
        }
    }

    __syncthreads();

    // ---- Pass 1: scores[p] = <ref_patch_p, main> ----
    float sc[K * K];
    #pragma unroll
    for (int p = 0; p < K * K; p++) sc[p] = 0.f;

    const float* rbase = refs + py * HW + px;
    #pragma unroll
    for (int c = 0; c < C; c++) {
        float mc = m[c];
        #pragma unroll
        for (int dh = 0; dh < K; dh++) {
            #pragma unroll
            for (int dw = 0; dw < K; dw++) {
                sc[dh * K + dw] = fmaf(rbase[c * CS + dh * HW + dw], mc, sc[dh * K + dw]);
            }
        }
    }

    // ---- Softmax over 49 positions (OOB positions carry score 0, included) ----
    float mx = sc[0];
    #pragma unroll
    for (int p = 1; p < K * K; p++) mx = fmaxf(mx, sc[p]);
    float sum = 0.f;
    #pragma unroll
    for (int p = 0; p < K * K; p++) {
        sc[p] = __expf(sc[p] - mx);
        sum += sc[p];
    }
    float inv = 1.f / sum;
    #pragma unroll
    for (int p = 0; p < K * K; p++) sc[p] *= inv;

    // All pass-1 reads of refs are complete before we overwrite it with trans.
    __syncthreads();

    // ---- Pass 2: out[c] = sum_p w[p] * val_patch_p[c]; write to trans smem ----
    const float* vbase = vals + py * HW + px;
    #pragma unroll
    for (int c = 0; c < C; c++) {
        float acc = 0.f;
        #pragma unroll
        for (int dh = 0; dh < K; dh++) {
            #pragma unroll
            for (int dw = 0; dw < K; dw++) {
                acc = fmaf(sc[dh * K + dw], vbase[c * CS + dh * HW + dw], acc);
            }
        }
        trans[tid * 33 + c] = acc;   // stride 33 -> conflict-free (lane+c distinct banks)
    }

    __syncthreads();

    // ---- Coalesced writeout: warp reads one pixel's 32 channels contiguously ----
    for (int idx = tid; idx < TY * TX * C; idx += NTHREADS) {
        int c = idx & 31;
        int p2 = idx >> 5;           // pixel index in tile, 0..127
        float o = trans[p2 * 33 + c];
        int py2 = p2 >> 5, px2 = p2 & 31;
        int g = (((by * TY + py2) << 8) + bx * TX + px2) * C + c;
        out[g] = o;
    }
}

extern "C" void kernel_launch(void* const* d_in, const int* in_sizes, int n_in,
                              void* d_out, int out_size) {
    const float* main_in = (const float*)d_in[0];
    const float* ref_in  = (const float*)d_in[1];
    const float* val_in  = (const float*)d_in[2];
    // d_in[3] is k_size (int32) == 7, baked in at compile time.
    float* out = (float*)d_out;

    cudaFuncSetAttribute(local_attn_kernel,
                         cudaFuncAttributeMaxDynamicSharedMemorySize, SMEM_BYTES);

    dim3 grid(W_IMG / TX, H_IMG / TY);
    local_attn_kernel<<<grid, NTHREADS, SMEM_BYTES>>>(main_in, ref_in, val_in, out);
}

// round 2
// speedup vs baseline: 1.0655x; 1.0655x over previous
#include <cuda_runtime.h>

// Windowed local attention, k=7, H=W=256, C=32, fp32.
// Tile: 32x4 pixels, 128 threads, ONE halo buffer (48.8KB) reused for
// ref (pass 1) then val (pass 2) -> 4 blocks/SM, 16 warps.

#define H_IMG 256
#define W_IMG 256
#define C 32
#define K 7
#define PAD 3
#define TX 32
#define TY 4
#define HW 38              // TX + K - 1
#define HH 10              // TY + K - 1
#define CS 381             // HW*HH = 380, +1 pad (odd -> conflict-free staging)
#define NTHREADS 128
#define SMEM_BYTES (C * CS * 4)

// Stage one tensor's halo into smem, channel-major, zero-padded OOB.
__device__ __forceinline__ void stage_halo(float* __restrict__ buf,
                                           const float* __restrict__ src,
                                           int bx, int by, int tid) {
    for (int idx = tid; idx < HW * HH * (C / 4); idx += NTHREADS) {
        int cg = idx & 7;                 // channel group (4 ch each)
        int wp = (idx >> 3) % HW;
        int hp = (idx >> 3) / HW;
        int gw = bx * TX - PAD + wp;
        int gh = by * TY - PAD + hp;
        float4 r = make_float4(0.f, 0.f, 0.f, 0.f);
        if (gw >= 0 && gw < W_IMG && gh >= 0 && gh < H_IMG) {
            r = *reinterpret_cast<const float4*>(src + ((gh << 8) + gw) * C + (cg << 2));
        }
        int s = hp * HW + wp;
        int c0 = cg << 2;
        buf[(c0 + 0) * CS + s] = r.x;
        buf[(c0 + 1) * CS + s] = r.y;
        buf[(c0 + 2) * CS + s] = r.z;
        buf[(c0 + 3) * CS + s] = r.w;
    }
}

__global__ __launch_bounds__(NTHREADS, 4)
void local_attn_kernel(const float* __restrict__ main_in,
                       const float* __restrict__ ref_in,
                       const float* __restrict__ val_in,
                       float* __restrict__ out) {
    extern __shared__ float smem[];
    float* buf = smem;               // [C][CS], holds ref then val then transpose

    const int tid = threadIdx.x;
    const int bx = blockIdx.x, by = blockIdx.y;
    const int px = tid & 31;         // lane
    const int py = tid >> 5;         // warp id = row in tile

    // ---- Phase A: stage ref halo ----
    stage_halo(buf, ref_in, bx, by, tid);

    // ---- Load this pixel's query (main) into registers ----
    float m[C];
    {
        int g = (((by * TY + py) << 8) + bx * TX + px) * C;
        #pragma unroll
        for (int i = 0; i < C / 4; i++) {
            float4 t = *reinterpret_cast<const float4*>(main_in + g + 4 * i);
            m[4 * i + 0] = t.x;
            m[4 * i + 1] = t.y;
            m[4 * i + 2] = t.z;
            m[4 * i + 3] = t.w;
        }
    }

    __syncthreads();

    // ---- Pass 1: scores[p] = <ref_patch_p, main> ----
    float sc[K * K];
    #pragma unroll
    for (int p = 0; p < K * K; p++) sc[p] = 0.f;

    const float* rbase = buf + py * HW + px;
    #pragma unroll
    for (int c = 0; c < C; c++) {
        float mc = m[c];
        #pragma unroll
        for (int dh = 0; dh < K; dh++) {
            #pragma unroll
            for (int dw = 0; dw < K; dw++) {
                sc[dh * K + dw] = fmaf(rbase[c * CS + dh * HW + dw], mc, sc[dh * K + dw]);
            }
        }
    }

    // ---- Softmax over 49 positions (OOB positions carry score 0, included) ----
    float mx = sc[0];
    #pragma unroll
    for (int p = 1; p < K * K; p++) mx = fmaxf(mx, sc[p]);
    float sum = 0.f;
    #pragma unroll
    for (int p = 0; p < K * K; p++) {
        sc[p] = __expf(sc[p] - mx);
        sum += sc[p];
    }
    float inv = 1.f / sum;
    #pragma unroll
    for (int p = 0; p < K * K; p++) sc[p] *= inv;

    // ---- Phase B: overwrite buffer with val halo ----
    __syncthreads();                 // all pass-1 reads done
    stage_halo(buf, val_in, bx, by, tid);
    __syncthreads();

    // ---- Pass 2: out[c] = sum_p w[p] * val_patch_p[c] ----
    float acc[C];
    const float* vbase = buf + py * HW + px;
    #pragma unroll
    for (int c = 0; c < C; c++) {
        float a = 0.f;
        #pragma unroll
        for (int dh = 0; dh < K; dh++) {
            #pragma unroll
            for (int dw = 0; dw < K; dw++) {
                a = fmaf(sc[dh * K + dw], vbase[c * CS + dh * HW + dw], a);
            }
        }
        acc[c] = a;
    }

    // ---- Transpose through smem for coalesced writeout ----
    __syncthreads();                 // all pass-2 reads done
    #pragma unroll
    for (int c = 0; c < C; c++) buf[tid * 33 + c] = acc[c];
    __syncthreads();

    for (int idx = tid; idx < TY * TX * C; idx += NTHREADS) {
        int c = idx & 31;
        int p2 = idx >> 5;           // pixel index in tile
        int py2 = p2 >> 5, px2 = p2 & 31;
        int g = (((by * TY + py2) << 8) + bx * TX + px2) * C + c;
        out[g] = buf[p2 * 33 + c];
    }
}

extern "C" void kernel_launch(void* const* d_in, const int* in_sizes, int n_in,
                              void* d_out, int out_size) {
    const float* main_in = (const float*)d_in[0];
    const float* ref_in  = (const float*)d_in[1];
    const float* val_in  = (const float*)d_in[2];
    float* out = (float*)d_out;

    cudaFuncSetAttribute(local_attn_kernel,
                         cudaFuncAttributeMaxDynamicSharedMemorySize, SMEM_BYTES);

    dim3 grid(W_IMG / TX, H_IMG / TY);
    local_attn_kernel<<<grid, NTHREADS, SMEM_BYTES>>>(main_in, ref_in, val_in, out);
}